// round 15
// baseline (speedup 1.0000x reference)
#include <cuda_runtime.h>
#include <cuda_fp16.h>
#include <cstdint>

#define BATCH 4
#define SEQ   2048
#define EMB   1024
#define HD    64
#define NQC2  32                 // per-warp (64-row) z-partial chunks

// Scratch (allocation-free: __device__ globals)
static __device__ __half g_wh[BATCH * SEQ * SEQ];     // 32 MB fp16: e = exp(s)
static __device__ __half g_hh[BATCH * SEQ * EMB];     // 16 MB fp16 h row-major
static __device__ __half g_hht[BATCH * EMB * SEQ];    // 16 MB fp16 h^T; scaled by f in place
static __device__ __half g_qh[BATCH * SEQ * HD];      // 1 MB fp16 q
static __device__ __half g_kh[BATCH * SEQ * HD];      // 1 MB fp16 k
static __device__ __half g_wqkt[128 * EMB];           // 256 KB fp16 [Wq|Wk]^T : [n][e]
static __device__ float  g_f[BATCH * SEQ];            // 32 KB fp32 factor[b][col] = 1/z
static __device__ float  g_pz[NQC2 * BATCH * SEQ];    // tile sum-exp partials

__device__ __forceinline__ void cp_async16(uint32_t saddr, const void* gaddr) {
    asm volatile("cp.async.cg.shared.global [%0], [%1], 16;"
                 :: "r"(saddr), "l"(gaddr) : "memory");
}
__device__ __forceinline__ uint32_t smem_u32(const void* p) {
    uint32_t a;
    asm("{ .reg .u64 t; cvta.to.shared.u64 t, %1; cvt.u32.u64 %0, t; }"
        : "=r"(a) : "l"(p));
    return a;
}
__device__ __forceinline__ void mma_f16(float* c, const uint32_t* a, const uint32_t* b) {
    asm volatile(
        "mma.sync.aligned.m16n8k16.row.col.f32.f16.f16.f32 "
        "{%0,%1,%2,%3}, {%4,%5,%6,%7}, {%8,%9}, {%0,%1,%2,%3};"
        : "+f"(c[0]), "+f"(c[1]), "+f"(c[2]), "+f"(c[3])
        : "r"(a[0]), "r"(a[1]), "r"(a[2]), "r"(a[3]), "r"(b[0]), "r"(b[1]));
}
__device__ __forceinline__ void ldsm_x4(uint32_t* r, uint32_t saddr) {
    asm volatile("ldmatrix.sync.aligned.m8n8.x4.shared.b16 {%0,%1,%2,%3}, [%4];"
        : "=r"(r[0]), "=r"(r[1]), "=r"(r[2]), "=r"(r[3]) : "r"(saddr));
}

// ---------------------------------------------------------------------------
// Kernel 0a: h -> g_hh (fp16 row-major) and g_hht (fp16 transposed)
// ---------------------------------------------------------------------------
__global__ __launch_bounds__(256) void conv_h_kernel(const float* __restrict__ h)
{
    __shared__ float tile[64][33];
    const int b  = blockIdx.z;
    const int s0 = blockIdx.x * 64;
    const int e0 = blockIdx.y * 32;
    const int tid = threadIdx.x;
    const float* src = h + ((size_t)b * SEQ + s0) * EMB + e0;

    {
        const int r  = tid >> 2;
        const int c8 = (tid & 3) * 8;
        float4 v0 = *(const float4*)(src + (size_t)r * EMB + c8);
        float4 v1 = *(const float4*)(src + (size_t)r * EMB + c8 + 4);
        tile[r][c8 + 0] = v0.x; tile[r][c8 + 1] = v0.y;
        tile[r][c8 + 2] = v0.z; tile[r][c8 + 3] = v0.w;
        tile[r][c8 + 4] = v1.x; tile[r][c8 + 5] = v1.y;
        tile[r][c8 + 6] = v1.z; tile[r][c8 + 7] = v1.w;
        __half2 hp[4];
        hp[0] = __floats2half2_rn(v0.x, v0.y); hp[1] = __floats2half2_rn(v0.z, v0.w);
        hp[2] = __floats2half2_rn(v1.x, v1.y); hp[3] = __floats2half2_rn(v1.z, v1.w);
        *(uint4*)(g_hh + ((size_t)b * SEQ + s0 + r) * EMB + e0 + c8) = *(uint4*)hp;
    }
    __syncthreads();
    {
        const int e = tid >> 3;
        const int g = tid & 7;
        __half2 hp[4];
        #pragma unroll
        for (int i = 0; i < 4; i++)
            hp[i] = __floats2half2_rn(tile[g * 8 + 2 * i][e], tile[g * 8 + 2 * i + 1][e]);
        *(uint4*)(g_hht + ((size_t)b * EMB + e0 + e) * SEQ + s0 + g * 8) = *(uint4*)hp;
    }
}

// ---------------------------------------------------------------------------
// Kernel 0b: g_wqkt[n][e] = fp16( n<64 ? Wq[e][n] : Wk[e][n-64] )
// ---------------------------------------------------------------------------
__global__ __launch_bounds__(256) void conv_w_kernel(
    const float* __restrict__ Wq, const float* __restrict__ Wk)
{
    const int col = blockIdx.x;
    const float* W = (col < 64) ? Wq : Wk;
    const int c = col & 63;
    for (int e = threadIdx.x; e < EMB; e += 256)
        g_wqkt[col * EMB + e] = __float2half(W[(size_t)e * HD + c]);
}

// ---------------------------------------------------------------------------
// Kernel 1: [q|k] = g_hh @ [Wq|Wk] + [bq|bk]  via fp16 mma + ldmatrix.
// CTA tile M=64 x N=128, grid 128. K-chunk 64, double buffer.
// ---------------------------------------------------------------------------
#define PJA_BYTES (64 * 144)
#define PJB_BYTES (128 * 144)
#define PJ_STAGE  (PJA_BYTES + PJB_BYTES)
#define PJ_TOT    (2 * PJ_STAGE)

__global__ __launch_bounds__(256) void proj_f16_kernel(
    const float* __restrict__ bq, const float* __restrict__ bk)
{
    extern __shared__ char smem[];
    const uint32_t smem_base = smem_u32(smem);
    const int tid  = threadIdx.x;
    const int wid  = tid >> 5;
    const int lane = tid & 31;
    const int la   = lane >> 2, lb = lane & 3;
    const int wm   = (wid & 1) * 32;
    const int wn   = (wid >> 1) * 32;
    const int m0   = blockIdx.x * 64;
    const __half* A = g_hh + (size_t)m0 * EMB;

    const int lrow = lane & 15;
    const int lkof = (lane >> 4) * 8;
    const int brow = ((lane >> 4) & 1) * 8 + (lane & 7);
    const int bkof = ((lane >> 3) & 1) * 8;

    float acc[2][4][4];
    #pragma unroll
    for (int i = 0; i < 2; i++)
        #pragma unroll
        for (int j = 0; j < 4; j++)
            #pragma unroll
            for (int q = 0; q < 4; q++) acc[i][j][q] = 0.0f;

    #pragma unroll
    for (int i = 0; i < 2; i++) {
        const int idx = tid + i * 256;
        const int row = idx >> 3, ch = idx & 7;
        cp_async16(smem_base + row * 144 + ch * 16, A + (size_t)row * EMB + ch * 8);
    }
    #pragma unroll
    for (int i = 0; i < 4; i++) {
        const int idx = tid + i * 256;
        const int row = idx >> 3, ch = idx & 7;
        cp_async16(smem_base + PJA_BYTES + row * 144 + ch * 16,
                   g_wqkt + (size_t)row * EMB + ch * 8);
    }
    asm volatile("cp.async.commit_group;" ::: "memory");

    for (int c = 0; c < EMB / 64; ++c) {
        const int p = c & 1;
        if (c < EMB / 64 - 1) {
            const int k0 = (c + 1) * 64;
            const uint32_t st = smem_base + (p ^ 1) * PJ_STAGE;
            #pragma unroll
            for (int i = 0; i < 2; i++) {
                const int idx = tid + i * 256;
                const int row = idx >> 3, ch = idx & 7;
                cp_async16(st + row * 144 + ch * 16, A + (size_t)row * EMB + k0 + ch * 8);
            }
            #pragma unroll
            for (int i = 0; i < 4; i++) {
                const int idx = tid + i * 256;
                const int row = idx >> 3, ch = idx & 7;
                cp_async16(st + PJA_BYTES + row * 144 + ch * 16,
                           g_wqkt + (size_t)row * EMB + k0 + ch * 8);
            }
            asm volatile("cp.async.commit_group;" ::: "memory");
            asm volatile("cp.async.wait_group 1;" ::: "memory");
        } else {
            asm volatile("cp.async.wait_group 0;" ::: "memory");
        }
        __syncthreads();

        const uint32_t sAb = smem_base + p * PJ_STAGE;
        const uint32_t sBb = sAb + PJA_BYTES;

        #pragma unroll
        for (int kf = 0; kf < 4; kf++) {
            uint32_t afr[2][4];
            #pragma unroll
            for (int mf = 0; mf < 2; mf++)
                ldsm_x4(afr[mf], sAb + (wm + mf * 16 + lrow) * 144 + (kf * 16 + lkof) * 2);
            uint32_t bfr[4][2];
            #pragma unroll
            for (int nfp = 0; nfp < 2; nfp++)
                ldsm_x4(&bfr[nfp * 2][0],
                        sBb + (wn + nfp * 16 + brow) * 144 + (kf * 16 + bkof) * 2);
            #pragma unroll
            for (int mf = 0; mf < 2; mf++)
                #pragma unroll
                for (int nf = 0; nf < 4; nf++)
                    mma_f16(acc[mf][nf], afr[mf], bfr[nf]);
        }
        __syncthreads();
    }

    #pragma unroll
    for (int mf = 0; mf < 2; mf++) {
        const int r0 = m0 + wm + mf * 16 + la;
        #pragma unroll
        for (int nf = 0; nf < 4; nf++) {
            const int cn = wn + nf * 8 + lb * 2;
            __half* dst; float b0v, b1v; int cc;
            if (cn < 64) { dst = g_qh; cc = cn;      b0v = bq[cc]; b1v = bq[cc + 1]; }
            else         { dst = g_kh; cc = cn - 64; b0v = bk[cc]; b1v = bk[cc + 1]; }
            __half2 h0 = __floats2half2_rn(acc[mf][nf][0] + b0v, acc[mf][nf][1] + b1v);
            __half2 h1 = __floats2half2_rn(acc[mf][nf][2] + b0v, acc[mf][nf][3] + b1v);
            *(__half2*)(dst + (size_t)r0 * HD + cc)       = h0;
            *(__half2*)(dst + (size_t)(r0 + 8) * HD + cc) = h1;
        }
    }
}

// ---------------------------------------------------------------------------
// Kernel 2: e = exp(q@k^T * 0.125) -> g_wh (fp16), via smem restage for
// coalesced 16B stores; per-warp column z partials via lane shuffles.
// ---------------------------------------------------------------------------
#define SCQ_BYTES (128 * 144)
#define SC_TOT    (2 * SCQ_BYTES)    // 36864; restage needs 34816 <= SC_TOT

__global__ __launch_bounds__(256) void score_f16_kernel()
{
    extern __shared__ char smem[];
    const uint32_t smem_base = smem_u32(smem);
    const int tid  = threadIdx.x;
    const int wid  = tid >> 5;
    const int lane = tid & 31;
    const int la   = lane >> 2, lb = lane & 3;
    const int wm   = (wid & 1) * 64;
    const int wn   = (wid >> 1) * 32;
    const int b    = blockIdx.z;
    const int m0   = blockIdx.y * 128;
    const int n0   = blockIdx.x * 128;
    const __half* qg = g_qh + ((size_t)b * SEQ + m0) * HD;
    const __half* kg = g_kh + ((size_t)b * SEQ + n0) * HD;

    const int lrow = lane & 15;
    const int lkof = (lane >> 4) * 8;
    const int brow = ((lane >> 4) & 1) * 8 + (lane & 7);
    const int bkof = ((lane >> 3) & 1) * 8;

    #pragma unroll
    for (int i = 0; i < 4; i++) {
        const int idx = tid + i * 256;
        const int row = idx >> 3, ch = idx & 7;
        cp_async16(smem_base + row * 144 + ch * 16, qg + (size_t)row * HD + ch * 8);
        cp_async16(smem_base + SCQ_BYTES + row * 144 + ch * 16, kg + (size_t)row * HD + ch * 8);
    }
    asm volatile("cp.async.commit_group;" ::: "memory");
    asm volatile("cp.async.wait_group 0;" ::: "memory");
    __syncthreads();

    float acc[4][4][4];
    #pragma unroll
    for (int i = 0; i < 4; i++)
        #pragma unroll
        for (int j = 0; j < 4; j++)
            #pragma unroll
            for (int q = 0; q < 4; q++) acc[i][j][q] = 0.0f;

    #pragma unroll
    for (int kf = 0; kf < 4; kf++) {
        uint32_t afr[4][4];
        #pragma unroll
        for (int mf = 0; mf < 4; mf++)
            ldsm_x4(afr[mf], smem_base + (wm + mf * 16 + lrow) * 144 + (kf * 16 + lkof) * 2);
        uint32_t bfr[4][2];
        #pragma unroll
        for (int nfp = 0; nfp < 2; nfp++)
            ldsm_x4(&bfr[nfp * 2][0],
                    smem_base + SCQ_BYTES + (wn + nfp * 16 + brow) * 144 + (kf * 16 + bkof) * 2);
        #pragma unroll
        for (int mf = 0; mf < 4; mf++)
            #pragma unroll
            for (int nf = 0; nf < 4; nf++)
                mma_f16(acc[mf][nf], afr[mf], bfr[nf]);
    }

    // e = exp(0.125 * s); per-warp column z partials (shuffle-only)
    const int qc = (m0 + wm) >> 6;
    #pragma unroll
    for (int nf = 0; nf < 4; nf++) {
        #pragma unroll
        for (int e = 0; e < 2; e++) {
            float z = 0.0f;
            #pragma unroll
            for (int mf = 0; mf < 4; mf++) {
                float e0 = __expf(acc[mf][nf][e]     * 0.125f);
                float e1 = __expf(acc[mf][nf][e + 2] * 0.125f);
                acc[mf][nf][e]     = e0;
                acc[mf][nf][e + 2] = e1;
                z += e0 + e1;
            }
            #pragma unroll
            for (int off = 4; off <= 16; off <<= 1)
                z += __shfl_xor_sync(0xffffffffu, z, off);
            if (la == 0) {
                const int gi = qc * (BATCH * SEQ) + b * SEQ + n0 + wn + nf * 8 + lb * 2 + e;
                g_pz[gi] = z;
            }
        }
    }

    // restage tile into smem (272B padded rows)
    __syncthreads();
    #pragma unroll
    for (int mf = 0; mf < 4; mf++) {
        const int r0 = wm + mf * 16 + la;
        #pragma unroll
        for (int nf = 0; nf < 4; nf++) {
            const int cn = wn + nf * 8 + lb * 2;
            *(__half2*)(smem + r0 * 272 + cn * 2) =
                __floats2half2_rn(acc[mf][nf][0], acc[mf][nf][1]);
            *(__half2*)(smem + (r0 + 8) * 272 + cn * 2) =
                __floats2half2_rn(acc[mf][nf][2], acc[mf][nf][3]);
        }
    }
    __syncthreads();

    __half* E = g_wh + (size_t)b * SEQ * SEQ;
    #pragma unroll
    for (int i = 0; i < 8; i++) {
        const int idx = i * 256 + tid;
        const int row = idx >> 4;
        const int ch  = idx & 15;
        uint4 v = *(const uint4*)(smem + row * 272 + ch * 16);
        *(uint4*)(E + (size_t)(m0 + row) * SEQ + n0 + ch * 8) = v;
    }
}

// ---------------------------------------------------------------------------
// Kernel 3: merge partials -> g_f[b][col] = 1 / sum_qc z   (fp32)
// ---------------------------------------------------------------------------
__global__ __launch_bounds__(256) void colstat_merge_kernel()
{
    const int idx = blockIdx.x * 256 + threadIdx.x;
    float z = 0.0f;
    #pragma unroll
    for (int qc = 0; qc < NQC2; qc++)
        z += g_pz[qc * (BATCH * SEQ) + idx];
    g_f[idx] = 1.0f / z;
}

// ---------------------------------------------------------------------------
// Kernel 4: scale H^T in place: g_hht[b][e][k] = fp16( hht * f[b][k] )
// ---------------------------------------------------------------------------
__global__ __launch_bounds__(256) void scale_hht_kernel()
{
    const size_t idx = ((size_t)blockIdx.x * 256 + threadIdx.x) * 8;
    const int b   = (int)(idx >> 21);
    const int col = (int)idx & (SEQ - 1);
    uint4 e4 = *(const uint4*)(g_hht + idx);
    const float* f = g_f + b * SEQ + col;
    float4 f0 = *(const float4*)(f);
    float4 f1 = *(const float4*)(f + 4);
    const __half2* e2 = (const __half2*)&e4;
    __half2 w2[4];
    float2 t;
    t = __half22float2(e2[0]); w2[0] = __floats2half2_rn(t.x * f0.x, t.y * f0.y);
    t = __half22float2(e2[1]); w2[1] = __floats2half2_rn(t.x * f0.z, t.y * f0.w);
    t = __half22float2(e2[2]); w2[2] = __floats2half2_rn(t.x * f1.x, t.y * f1.y);
    t = __half22float2(e2[3]); w2[3] = __floats2half2_rn(t.x * f1.z, t.y * f1.w);
    *(uint4*)(g_hht + idx) = *(uint4*)w2;
}

// ---------------------------------------------------------------------------
// Kernel 5: out[b] = E[b] @ (f.*h)[b] via fp16 mma + ldmatrix.
// CTA 128x128, 4 WARPS (128 thr), warp tile 64x64 (less LDSM redundancy:
// A 2x, B 2x -> 101 KB crossbar/chunk vs 134 KB at 8 warps/64x32).
// K-chunk 64, TRIPLE buffer (110.6 KB smem, 2 CTAs/SM).
// ---------------------------------------------------------------------------
#define OROW     144
#define OA_BYTES (128 * OROW)
#define OB_BYTES (128 * OROW)
#define O_STAGE  (OA_BYTES + OB_BYTES)
#define O_NSTG   3
#define OSM_TOT  (O_NSTG * O_STAGE)
#define O_NC     (SEQ / 64)

__global__ __launch_bounds__(128) void out_gemm_f16_kernel(float* __restrict__ out)
{
    extern __shared__ char smem[];
    const uint32_t smem_base = smem_u32(smem);
    const int tid  = threadIdx.x;
    const int wid  = tid >> 5;
    const int lane = tid & 31;
    const int la   = lane >> 2;
    const int lb   = lane & 3;
    const int wm   = (wid & 1) * 64;
    const int wn   = (wid >> 1) * 64;

    const int b  = blockIdx.z;
    const int m0 = blockIdx.y * 128;
    const int n0 = blockIdx.x * 128;
    const __half* A  = g_wh  + (size_t)b * SEQ * SEQ + (size_t)m0 * SEQ;
    const __half* Bt = g_hht + (size_t)b * EMB * SEQ + (size_t)n0 * SEQ;

    const int lrow = lane & 15;
    const int lkof = (lane >> 4) * 8;
    const int brow = ((lane >> 4) & 1) * 8 + (lane & 7);
    const int bkof = ((lane >> 3) & 1) * 8;

    const int ldrow = tid >> 3, ldch = tid & 7;   // loader: 16 rows x 8 ch / pass

    float acc[4][8][4];
    #pragma unroll
    for (int i = 0; i < 4; i++)
        #pragma unroll
        for (int j = 0; j < 8; j++)
            #pragma unroll
            for (int q = 0; q < 4; q++) acc[i][j][q] = 0.0f;

    #pragma unroll
    for (int pc = 0; pc < 2; pc++) {
        const uint32_t st = smem_base + pc * O_STAGE;
        const int k0 = pc * 64;
        #pragma unroll
        for (int i = 0; i < 8; i++) {
            const int row = ldrow + i * 16;
            cp_async16(st + row * OROW + ldch * 16, A + (size_t)row * SEQ + k0 + ldch * 8);
            cp_async16(st + OA_BYTES + row * OROW + ldch * 16,
                       Bt + (size_t)row * SEQ + k0 + ldch * 8);
        }
        asm volatile("cp.async.commit_group;" ::: "memory");
    }

    int p = 0;
    for (int c = 0; c < O_NC; ++c) {
        if (c + 2 < O_NC) {
            int pn = p + 2;
            if (pn >= O_NSTG) pn -= O_NSTG;
            const uint32_t st = smem_base + pn * O_STAGE;
            const int k0 = (c + 2) * 64;
            #pragma unroll
            for (int i = 0; i < 8; i++) {
                const int row = ldrow + i * 16;
                cp_async16(st + row * OROW + ldch * 16, A + (size_t)row * SEQ + k0 + ldch * 8);
                cp_async16(st + OA_BYTES + row * OROW + ldch * 16,
                           Bt + (size_t)row * SEQ + k0 + ldch * 8);
            }
            asm volatile("cp.async.commit_group;" ::: "memory");
            asm volatile("cp.async.wait_group 2;" ::: "memory");
        } else if (c + 1 < O_NC) {
            asm volatile("cp.async.wait_group 1;" ::: "memory");
        } else {
            asm volatile("cp.async.wait_group 0;" ::: "memory");
        }
        __syncthreads();

        const uint32_t sAb = smem_base + p * O_STAGE;
        const uint32_t sBb = sAb + OA_BYTES;

        #pragma unroll
        for (int kf = 0; kf < 4; kf++) {
            uint32_t afr[4][4];
            #pragma unroll
            for (int mf = 0; mf < 4; mf++)
                ldsm_x4(afr[mf], sAb + (wm + mf * 16 + lrow) * OROW + (kf * 16 + lkof) * 2);
            uint32_t bfr[8][2];
            #pragma unroll
            for (int nfp = 0; nfp < 4; nfp++)
                ldsm_x4(&bfr[nfp * 2][0],
                        sBb + (wn + nfp * 16 + brow) * OROW + (kf * 16 + bkof) * 2);
            #pragma unroll
            for (int mf = 0; mf < 4; mf++)
                #pragma unroll
                for (int nf = 0; nf < 8; nf++)
                    mma_f16(acc[mf][nf], afr[mf], bfr[nf]);
        }
        __syncthreads();
        p = (p + 1 == O_NSTG) ? 0 : p + 1;
    }

    float* C = out + (size_t)b * SEQ * EMB;
    #pragma unroll
    for (int mf = 0; mf < 4; mf++) {
        const int r = m0 + wm + mf * 16 + la;
        #pragma unroll
        for (int nf = 0; nf < 8; nf++) {
            const int col = n0 + wn + nf * 8 + lb * 2;
            *(float2*)(C + (size_t)r * EMB + col)       = make_float2(acc[mf][nf][0], acc[mf][nf][1]);
            *(float2*)(C + (size_t)(r + 8) * EMB + col) = make_float2(acc[mf][nf][2], acc[mf][nf][3]);
        }
    }
}

// ---------------------------------------------------------------------------
extern "C" void kernel_launch(void* const* d_in, const int* in_sizes, int n_in,
                              void* d_out, int out_size)
{
    const float* h  = (const float*)d_in[0];
    const float* Wq = (const float*)d_in[1];
    const float* bq = (const float*)d_in[2];
    const float* Wk = (const float*)d_in[3];
    const float* bk = (const float*)d_in[4];
    float* out = (float*)d_out;

    static int smem_set = 0;
    if (!smem_set) {
        cudaFuncSetAttribute(out_gemm_f16_kernel,
                             cudaFuncAttributeMaxDynamicSharedMemorySize, OSM_TOT);
        cudaFuncSetAttribute(proj_f16_kernel,
                             cudaFuncAttributeMaxDynamicSharedMemorySize, PJ_TOT);
        cudaFuncSetAttribute(score_f16_kernel,
                             cudaFuncAttributeMaxDynamicSharedMemorySize, SC_TOT);
        smem_set = 1;
    }

    conv_h_kernel<<<dim3(SEQ / 64, EMB / 32, BATCH), 256>>>(h);
    conv_w_kernel<<<128, 256>>>(Wq, Wk);
    proj_f16_kernel<<<(BATCH * SEQ) / 64, 256, PJ_TOT>>>(bq, bk);
    score_f16_kernel<<<dim3(SEQ / 128, SEQ / 128, BATCH), 256, SC_TOT>>>();
    colstat_merge_kernel<<<(BATCH * SEQ) / 256, 256>>>();
    scale_hht_kernel<<<(int)(((size_t)BATCH * EMB * SEQ) / (8 * 256)), 256>>>();
    out_gemm_f16_kernel<<<dim3(EMB / 128, SEQ / 128, BATCH), 128, OSM_TOT>>>(out);
}

// round 16
// speedup vs baseline: 1.0408x; 1.0408x over previous
#include <cuda_runtime.h>
#include <cuda_fp16.h>
#include <cstdint>

#define BATCH 4
#define SEQ   2048
#define EMB   1024
#define HD    64
#define NQC2  32                 // per-warp (64-row) z-partial chunks

// Scratch (allocation-free: __device__ globals)
static __device__ __half g_wh[BATCH * SEQ * SEQ];     // 32 MB fp16: e = exp(s)
static __device__ __half g_hh[BATCH * SEQ * EMB];     // 16 MB fp16 h row-major
static __device__ __half g_hht[BATCH * EMB * SEQ];    // 16 MB fp16 h^T; scaled by f in place
static __device__ __half g_qh[BATCH * SEQ * HD];      // 1 MB fp16 q
static __device__ __half g_kh[BATCH * SEQ * HD];      // 1 MB fp16 k
static __device__ __half g_wqkt[128 * EMB];           // 256 KB fp16 [Wq|Wk]^T : [n][e]
static __device__ float  g_f[BATCH * SEQ];            // 32 KB fp32 factor[b][col] = 1/z
static __device__ float  g_pz[NQC2 * BATCH * SEQ];    // tile sum-exp partials

__device__ __forceinline__ void cp_async16(uint32_t saddr, const void* gaddr) {
    asm volatile("cp.async.cg.shared.global [%0], [%1], 16;"
                 :: "r"(saddr), "l"(gaddr) : "memory");
}
__device__ __forceinline__ uint32_t smem_u32(const void* p) {
    uint32_t a;
    asm("{ .reg .u64 t; cvta.to.shared.u64 t, %1; cvt.u32.u64 %0, t; }"
        : "=r"(a) : "l"(p));
    return a;
}
__device__ __forceinline__ void mma_f16(float* c, const uint32_t* a, const uint32_t* b) {
    asm volatile(
        "mma.sync.aligned.m16n8k16.row.col.f32.f16.f16.f32 "
        "{%0,%1,%2,%3}, {%4,%5,%6,%7}, {%8,%9}, {%0,%1,%2,%3};"
        : "+f"(c[0]), "+f"(c[1]), "+f"(c[2]), "+f"(c[3])
        : "r"(a[0]), "r"(a[1]), "r"(a[2]), "r"(a[3]), "r"(b[0]), "r"(b[1]));
}
__device__ __forceinline__ void ldsm_x4(uint32_t* r, uint32_t saddr) {
    asm volatile("ldmatrix.sync.aligned.m8n8.x4.shared.b16 {%0,%1,%2,%3}, [%4];"
        : "=r"(r[0]), "=r"(r[1]), "=r"(r[2]), "=r"(r[3]) : "r"(saddr));
}

// ---------------------------------------------------------------------------
// Kernel 0a: h -> g_hh (fp16 row-major) and g_hht (fp16 transposed)
// ---------------------------------------------------------------------------
__global__ __launch_bounds__(256) void conv_h_kernel(const float* __restrict__ h)
{
    __shared__ float tile[64][33];
    const int b  = blockIdx.z;
    const int s0 = blockIdx.x * 64;
    const int e0 = blockIdx.y * 32;
    const int tid = threadIdx.x;
    const float* src = h + ((size_t)b * SEQ + s0) * EMB + e0;

    {
        const int r  = tid >> 2;
        const int c8 = (tid & 3) * 8;
        float4 v0 = *(const float4*)(src + (size_t)r * EMB + c8);
        float4 v1 = *(const float4*)(src + (size_t)r * EMB + c8 + 4);
        tile[r][c8 + 0] = v0.x; tile[r][c8 + 1] = v0.y;
        tile[r][c8 + 2] = v0.z; tile[r][c8 + 3] = v0.w;
        tile[r][c8 + 4] = v1.x; tile[r][c8 + 5] = v1.y;
        tile[r][c8 + 6] = v1.z; tile[r][c8 + 7] = v1.w;
        __half2 hp[4];
        hp[0] = __floats2half2_rn(v0.x, v0.y); hp[1] = __floats2half2_rn(v0.z, v0.w);
        hp[2] = __floats2half2_rn(v1.x, v1.y); hp[3] = __floats2half2_rn(v1.z, v1.w);
        *(uint4*)(g_hh + ((size_t)b * SEQ + s0 + r) * EMB + e0 + c8) = *(uint4*)hp;
    }
    __syncthreads();
    {
        const int e = tid >> 3;
        const int g = tid & 7;
        __half2 hp[4];
        #pragma unroll
        for (int i = 0; i < 4; i++)
            hp[i] = __floats2half2_rn(tile[g * 8 + 2 * i][e], tile[g * 8 + 2 * i + 1][e]);
        *(uint4*)(g_hht + ((size_t)b * EMB + e0 + e) * SEQ + s0 + g * 8) = *(uint4*)hp;
    }
}

// ---------------------------------------------------------------------------
// Kernel 0b: g_wqkt[n][e] = fp16( n<64 ? Wq[e][n] : Wk[e][n-64] )
// Coalesced read (row-major W) -> padded smem transpose -> 16B writes.
// Grid: EMB/64 = 16 blocks; each handles 64 e-rows of both Wq and Wk.
// ---------------------------------------------------------------------------
__global__ __launch_bounds__(256) void conv_w_kernel(
    const float* __restrict__ Wq, const float* __restrict__ Wk)
{
    __shared__ __half sW[128][66];     // [n][e_local], pad 66 kills transpose conflicts
    const int e0  = blockIdx.x * 64;
    const int tid = threadIdx.x;
    const int er  = tid >> 2;          // local e row 0..63
    const int c16 = (tid & 3) * 16;    // 16-col group within 64

    // load Wq/Wk rows coalesced (4 x float4 each), store transposed to smem
    #pragma unroll
    for (int u = 0; u < 4; u++) {
        const int c = c16 + u * 4;
        float4 vq = *(const float4*)(Wq + (size_t)(e0 + er) * HD + c);
        float4 vk = *(const float4*)(Wk + (size_t)(e0 + er) * HD + c);
        sW[c + 0][er]      = __float2half(vq.x);
        sW[c + 1][er]      = __float2half(vq.y);
        sW[c + 2][er]      = __float2half(vq.z);
        sW[c + 3][er]      = __float2half(vq.w);
        sW[64 + c + 0][er] = __float2half(vk.x);
        sW[64 + c + 1][er] = __float2half(vk.y);
        sW[64 + c + 2][er] = __float2half(vk.z);
        sW[64 + c + 3][er] = __float2half(vk.w);
    }
    __syncthreads();

    // write out: 128 n-rows x 64 e, 16B contiguous stores
    #pragma unroll
    for (int i = 0; i < 4; i++) {
        const int idx = tid + i * 256;
        const int n = idx >> 3;            // 0..127
        const int g = idx & 7;             // 8-half chunk
        __half tmp[8];
        #pragma unroll
        for (int j = 0; j < 8; j++) tmp[j] = sW[n][g * 8 + j];
        *(uint4*)(g_wqkt + (size_t)n * EMB + e0 + g * 8) = *(uint4*)tmp;
    }
}

// ---------------------------------------------------------------------------
// Kernel 1: [q|k] = g_hh @ [Wq|Wk] + [bq|bk]  via fp16 mma + ldmatrix.
// CTA tile M=64 x N=128, grid 128. K-chunk 64, double buffer.
// ---------------------------------------------------------------------------
#define PJA_BYTES (64 * 144)
#define PJB_BYTES (128 * 144)
#define PJ_STAGE  (PJA_BYTES + PJB_BYTES)
#define PJ_TOT    (2 * PJ_STAGE)

__global__ __launch_bounds__(256) void proj_f16_kernel(
    const float* __restrict__ bq, const float* __restrict__ bk)
{
    extern __shared__ char smem[];
    const uint32_t smem_base = smem_u32(smem);
    const int tid  = threadIdx.x;
    const int wid  = tid >> 5;
    const int lane = tid & 31;
    const int la   = lane >> 2, lb = lane & 3;
    const int wm   = (wid & 1) * 32;
    const int wn   = (wid >> 1) * 32;
    const int m0   = blockIdx.x * 64;
    const __half* A = g_hh + (size_t)m0 * EMB;

    const int lrow = lane & 15;
    const int lkof = (lane >> 4) * 8;
    const int brow = ((lane >> 4) & 1) * 8 + (lane & 7);
    const int bkof = ((lane >> 3) & 1) * 8;

    float acc[2][4][4];
    #pragma unroll
    for (int i = 0; i < 2; i++)
        #pragma unroll
        for (int j = 0; j < 4; j++)
            #pragma unroll
            for (int q = 0; q < 4; q++) acc[i][j][q] = 0.0f;

    #pragma unroll
    for (int i = 0; i < 2; i++) {
        const int idx = tid + i * 256;
        const int row = idx >> 3, ch = idx & 7;
        cp_async16(smem_base + row * 144 + ch * 16, A + (size_t)row * EMB + ch * 8);
    }
    #pragma unroll
    for (int i = 0; i < 4; i++) {
        const int idx = tid + i * 256;
        const int row = idx >> 3, ch = idx & 7;
        cp_async16(smem_base + PJA_BYTES + row * 144 + ch * 16,
                   g_wqkt + (size_t)row * EMB + ch * 8);
    }
    asm volatile("cp.async.commit_group;" ::: "memory");

    for (int c = 0; c < EMB / 64; ++c) {
        const int p = c & 1;
        if (c < EMB / 64 - 1) {
            const int k0 = (c + 1) * 64;
            const uint32_t st = smem_base + (p ^ 1) * PJ_STAGE;
            #pragma unroll
            for (int i = 0; i < 2; i++) {
                const int idx = tid + i * 256;
                const int row = idx >> 3, ch = idx & 7;
                cp_async16(st + row * 144 + ch * 16, A + (size_t)row * EMB + k0 + ch * 8);
            }
            #pragma unroll
            for (int i = 0; i < 4; i++) {
                const int idx = tid + i * 256;
                const int row = idx >> 3, ch = idx & 7;
                cp_async16(st + PJA_BYTES + row * 144 + ch * 16,
                           g_wqkt + (size_t)row * EMB + k0 + ch * 8);
            }
            asm volatile("cp.async.commit_group;" ::: "memory");
            asm volatile("cp.async.wait_group 1;" ::: "memory");
        } else {
            asm volatile("cp.async.wait_group 0;" ::: "memory");
        }
        __syncthreads();

        const uint32_t sAb = smem_base + p * PJ_STAGE;
        const uint32_t sBb = sAb + PJA_BYTES;

        #pragma unroll
        for (int kf = 0; kf < 4; kf++) {
            uint32_t afr[2][4];
            #pragma unroll
            for (int mf = 0; mf < 2; mf++)
                ldsm_x4(afr[mf], sAb + (wm + mf * 16 + lrow) * 144 + (kf * 16 + lkof) * 2);
            uint32_t bfr[4][2];
            #pragma unroll
            for (int nfp = 0; nfp < 2; nfp++)
                ldsm_x4(&bfr[nfp * 2][0],
                        sBb + (wn + nfp * 16 + brow) * 144 + (kf * 16 + bkof) * 2);
            #pragma unroll
            for (int mf = 0; mf < 2; mf++)
                #pragma unroll
                for (int nf = 0; nf < 4; nf++)
                    mma_f16(acc[mf][nf], afr[mf], bfr[nf]);
        }
        __syncthreads();
    }

    #pragma unroll
    for (int mf = 0; mf < 2; mf++) {
        const int r0 = m0 + wm + mf * 16 + la;
        #pragma unroll
        for (int nf = 0; nf < 4; nf++) {
            const int cn = wn + nf * 8 + lb * 2;
            __half* dst; float b0v, b1v; int cc;
            if (cn < 64) { dst = g_qh; cc = cn;      b0v = bq[cc]; b1v = bq[cc + 1]; }
            else         { dst = g_kh; cc = cn - 64; b0v = bk[cc]; b1v = bk[cc + 1]; }
            __half2 h0 = __floats2half2_rn(acc[mf][nf][0] + b0v, acc[mf][nf][1] + b1v);
            __half2 h1 = __floats2half2_rn(acc[mf][nf][2] + b0v, acc[mf][nf][3] + b1v);
            *(__half2*)(dst + (size_t)r0 * HD + cc)       = h0;
            *(__half2*)(dst + (size_t)(r0 + 8) * HD + cc) = h1;
        }
    }
}

// ---------------------------------------------------------------------------
// Kernel 2: e = exp(q@k^T * 0.125) -> g_wh (fp16), via smem restage for
// coalesced 16B stores; per-warp column z partials via lane shuffles.
// ---------------------------------------------------------------------------
#define SCQ_BYTES (128 * 144)
#define SC_TOT    (2 * SCQ_BYTES)    // 36864; restage needs 34816 <= SC_TOT

__global__ __launch_bounds__(256) void score_f16_kernel()
{
    extern __shared__ char smem[];
    const uint32_t smem_base = smem_u32(smem);
    const int tid  = threadIdx.x;
    const int wid  = tid >> 5;
    const int lane = tid & 31;
    const int la   = lane >> 2, lb = lane & 3;
    const int wm   = (wid & 1) * 64;
    const int wn   = (wid >> 1) * 32;
    const int b    = blockIdx.z;
    const int m0   = blockIdx.y * 128;
    const int n0   = blockIdx.x * 128;
    const __half* qg = g_qh + ((size_t)b * SEQ + m0) * HD;
    const __half* kg = g_kh + ((size_t)b * SEQ + n0) * HD;

    const int lrow = lane & 15;
    const int lkof = (lane >> 4) * 8;
    const int brow = ((lane >> 4) & 1) * 8 + (lane & 7);
    const int bkof = ((lane >> 3) & 1) * 8;

    #pragma unroll
    for (int i = 0; i < 4; i++) {
        const int idx = tid + i * 256;
        const int row = idx >> 3, ch = idx & 7;
        cp_async16(smem_base + row * 144 + ch * 16, qg + (size_t)row * HD + ch * 8);
        cp_async16(smem_base + SCQ_BYTES + row * 144 + ch * 16, kg + (size_t)row * HD + ch * 8);
    }
    asm volatile("cp.async.commit_group;" ::: "memory");
    asm volatile("cp.async.wait_group 0;" ::: "memory");
    __syncthreads();

    float acc[4][4][4];
    #pragma unroll
    for (int i = 0; i < 4; i++)
        #pragma unroll
        for (int j = 0; j < 4; j++)
            #pragma unroll
            for (int q = 0; q < 4; q++) acc[i][j][q] = 0.0f;

    #pragma unroll
    for (int kf = 0; kf < 4; kf++) {
        uint32_t afr[4][4];
        #pragma unroll
        for (int mf = 0; mf < 4; mf++)
            ldsm_x4(afr[mf], smem_base + (wm + mf * 16 + lrow) * 144 + (kf * 16 + lkof) * 2);
        uint32_t bfr[4][2];
        #pragma unroll
        for (int nfp = 0; nfp < 2; nfp++)
            ldsm_x4(&bfr[nfp * 2][0],
                    smem_base + SCQ_BYTES + (wn + nfp * 16 + brow) * 144 + (kf * 16 + bkof) * 2);
        #pragma unroll
        for (int mf = 0; mf < 4; mf++)
            #pragma unroll
            for (int nf = 0; nf < 4; nf++)
                mma_f16(acc[mf][nf], afr[mf], bfr[nf]);
    }

    // e = exp(0.125 * s); per-warp column z partials (shuffle-only)
    const int qc = (m0 + wm) >> 6;
    #pragma unroll
    for (int nf = 0; nf < 4; nf++) {
        #pragma unroll
        for (int e = 0; e < 2; e++) {
            float z = 0.0f;
            #pragma unroll
            for (int mf = 0; mf < 4; mf++) {
                float e0 = __expf(acc[mf][nf][e]     * 0.125f);
                float e1 = __expf(acc[mf][nf][e + 2] * 0.125f);
                acc[mf][nf][e]     = e0;
                acc[mf][nf][e + 2] = e1;
                z += e0 + e1;
            }
            #pragma unroll
            for (int off = 4; off <= 16; off <<= 1)
                z += __shfl_xor_sync(0xffffffffu, z, off);
            if (la == 0) {
                const int gi = qc * (BATCH * SEQ) + b * SEQ + n0 + wn + nf * 8 + lb * 2 + e;
                g_pz[gi] = z;
            }
        }
    }

    // restage tile into smem (272B padded rows)
    __syncthreads();
    #pragma unroll
    for (int mf = 0; mf < 4; mf++) {
        const int r0 = wm + mf * 16 + la;
        #pragma unroll
        for (int nf = 0; nf < 4; nf++) {
            const int cn = wn + nf * 8 + lb * 2;
            *(__half2*)(smem + r0 * 272 + cn * 2) =
                __floats2half2_rn(acc[mf][nf][0], acc[mf][nf][1]);
            *(__half2*)(smem + (r0 + 8) * 272 + cn * 2) =
                __floats2half2_rn(acc[mf][nf][2], acc[mf][nf][3]);
        }
    }
    __syncthreads();

    __half* E = g_wh + (size_t)b * SEQ * SEQ;
    #pragma unroll
    for (int i = 0; i < 8; i++) {
        const int idx = i * 256 + tid;
        const int row = idx >> 4;
        const int ch  = idx & 15;
        uint4 v = *(const uint4*)(smem + row * 272 + ch * 16);
        *(uint4*)(E + (size_t)(m0 + row) * SEQ + n0 + ch * 8) = v;
    }
}

// ---------------------------------------------------------------------------
// Kernel 3: merge partials -> g_f[b][col] = 1 / sum_qc z   (fp32)
// ---------------------------------------------------------------------------
__global__ __launch_bounds__(256) void colstat_merge_kernel()
{
    const int idx = blockIdx.x * 256 + threadIdx.x;
    float z = 0.0f;
    #pragma unroll
    for (int qc = 0; qc < NQC2; qc++)
        z += g_pz[qc * (BATCH * SEQ) + idx];
    g_f[idx] = 1.0f / z;
}

// ---------------------------------------------------------------------------
// Kernel 4: scale H^T in place: g_hht[b][e][k] = fp16( hht * f[b][k] )
// ---------------------------------------------------------------------------
__global__ __launch_bounds__(256) void scale_hht_kernel()
{
    const size_t idx = ((size_t)blockIdx.x * 256 + threadIdx.x) * 8;
    const int b   = (int)(idx >> 21);
    const int col = (int)idx & (SEQ - 1);
    uint4 e4 = *(const uint4*)(g_hht + idx);
    const float* f = g_f + b * SEQ + col;
    float4 f0 = *(const float4*)(f);
    float4 f1 = *(const float4*)(f + 4);
    const __half2* e2 = (const __half2*)&e4;
    __half2 w2[4];
    float2 t;
    t = __half22float2(e2[0]); w2[0] = __floats2half2_rn(t.x * f0.x, t.y * f0.y);
    t = __half22float2(e2[1]); w2[1] = __floats2half2_rn(t.x * f0.z, t.y * f0.w);
    t = __half22float2(e2[2]); w2[2] = __floats2half2_rn(t.x * f1.x, t.y * f1.y);
    t = __half22float2(e2[3]); w2[3] = __floats2half2_rn(t.x * f1.z, t.y * f1.w);
    *(uint4*)(g_hht + idx) = *(uint4*)w2;
}

// ---------------------------------------------------------------------------
// Kernel 5: out[b] = E[b] @ (f.*h)[b] via fp16 mma + ldmatrix.
// CTA 128x128, 8 warps (2m x 4n), warp tile 64x32, K-chunk 64,
// TRIPLE buffer (110.6 KB smem, 2 CTAs/SM).   [R14 proven optimum]
// ---------------------------------------------------------------------------
#define OROW     144
#define OA_BYTES (128 * OROW)
#define OB_BYTES (128 * OROW)
#define O_STAGE  (OA_BYTES + OB_BYTES)
#define O_NSTG   3
#define OSM_TOT  (O_NSTG * O_STAGE)
#define O_NC     (SEQ / 64)

__global__ __launch_bounds__(256, 2) void out_gemm_f16_kernel(float* __restrict__ out)
{
    extern __shared__ char smem[];
    const uint32_t smem_base = smem_u32(smem);
    const int tid  = threadIdx.x;
    const int wid  = tid >> 5;
    const int lane = tid & 31;
    const int la   = lane >> 2;
    const int lb   = lane & 3;
    const int wm   = (wid & 1) * 64;
    const int wn   = (wid >> 1) * 32;

    const int b  = blockIdx.z;
    const int m0 = blockIdx.y * 128;
    const int n0 = blockIdx.x * 128;
    const __half* A  = g_wh  + (size_t)b * SEQ * SEQ + (size_t)m0 * SEQ;
    const __half* Bt = g_hht + (size_t)b * EMB * SEQ + (size_t)n0 * SEQ;

    const int lrow = lane & 15;
    const int lkof = (lane >> 4) * 8;
    const int brow = ((lane >> 4) & 1) * 8 + (lane & 7);
    const int bkof = ((lane >> 3) & 1) * 8;

    const int ldrow = tid >> 3, ldch = tid & 7;

    float acc[4][4][4];
    #pragma unroll
    for (int i = 0; i < 4; i++)
        #pragma unroll
        for (int j = 0; j < 4; j++)
            #pragma unroll
            for (int q = 0; q < 4; q++) acc[i][j][q] = 0.0f;

    #pragma unroll
    for (int pc = 0; pc < 2; pc++) {
        const uint32_t st = smem_base + pc * O_STAGE;
        const int k0 = pc * 64;
        #pragma unroll
        for (int i = 0; i < 4; i++) {
            const int row = ldrow + i * 32;
            cp_async16(st + row * OROW + ldch * 16, A + (size_t)row * SEQ + k0 + ldch * 8);
            cp_async16(st + OA_BYTES + row * OROW + ldch * 16,
                       Bt + (size_t)row * SEQ + k0 + ldch * 8);
        }
        asm volatile("cp.async.commit_group;" ::: "memory");
    }

    int p = 0;
    for (int c = 0; c < O_NC; ++c) {
        if (c + 2 < O_NC) {
            int pn = p + 2;
            if (pn >= O_NSTG) pn -= O_NSTG;
            const uint32_t st = smem_base + pn * O_STAGE;
            const int k0 = (c + 2) * 64;
            #pragma unroll
            for (int i = 0; i < 4; i++) {
                const int row = ldrow + i * 32;
                cp_async16(st + row * OROW + ldch * 16, A + (size_t)row * SEQ + k0 + ldch * 8);
                cp_async16(st + OA_BYTES + row * OROW + ldch * 16,
                           Bt + (size_t)row * SEQ + k0 + ldch * 8);
            }
            asm volatile("cp.async.commit_group;" ::: "memory");
            asm volatile("cp.async.wait_group 2;" ::: "memory");
        } else if (c + 1 < O_NC) {
            asm volatile("cp.async.wait_group 1;" ::: "memory");
        } else {
            asm volatile("cp.async.wait_group 0;" ::: "memory");
        }
        __syncthreads();

        const uint32_t sAb = smem_base + p * O_STAGE;
        const uint32_t sBb = sAb + OA_BYTES;

        #pragma unroll
        for (int kf = 0; kf < 4; kf++) {
            uint32_t afr[4][4];
            #pragma unroll
            for (int mf = 0; mf < 4; mf++)
                ldsm_x4(afr[mf], sAb + (wm + mf * 16 + lrow) * OROW + (kf * 16 + lkof) * 2);
            uint32_t bfr[4][2];
            #pragma unroll
            for (int nfp = 0; nfp < 2; nfp++)
                ldsm_x4(&bfr[nfp * 2][0],
                        sBb + (wn + nfp * 16 + brow) * OROW + (kf * 16 + bkof) * 2);
            #pragma unroll
            for (int mf = 0; mf < 4; mf++)
                #pragma unroll
                for (int nf = 0; nf < 4; nf++)
                    mma_f16(acc[mf][nf], afr[mf], bfr[nf]);
        }
        __syncthreads();
        p = (p + 1 == O_NSTG) ? 0 : p + 1;
    }

    float* C = out + (size_t)b * SEQ * EMB;
    #pragma unroll
    for (int mf = 0; mf < 4; mf++) {
        const int r = m0 + wm + mf * 16 + la;
        #pragma unroll
        for (int nf = 0; nf < 4; nf++) {
            const int col = n0 + wn + nf * 8 + lb * 2;
            *(float2*)(C + (size_t)r * EMB + col)       = make_float2(acc[mf][nf][0], acc[mf][nf][1]);
            *(float2*)(C + (size_t)(r + 8) * EMB + col) = make_float2(acc[mf][nf][2], acc[mf][nf][3]);
        }
    }
}

// ---------------------------------------------------------------------------
extern "C" void kernel_launch(void* const* d_in, const int* in_sizes, int n_in,
                              void* d_out, int out_size)
{
    const float* h  = (const float*)d_in[0];
    const float* Wq = (const float*)d_in[1];
    const float* bq = (const float*)d_in[2];
    const float* Wk = (const float*)d_in[3];
    const float* bk = (const float*)d_in[4];
    float* out = (float*)d_out;

    static int smem_set = 0;
    if (!smem_set) {
        cudaFuncSetAttribute(out_gemm_f16_kernel,
                             cudaFuncAttributeMaxDynamicSharedMemorySize, OSM_TOT);
        cudaFuncSetAttribute(proj_f16_kernel,
                             cudaFuncAttributeMaxDynamicSharedMemorySize, PJ_TOT);
        cudaFuncSetAttribute(score_f16_kernel,
                             cudaFuncAttributeMaxDynamicSharedMemorySize, SC_TOT);
        smem_set = 1;
    }

    conv_h_kernel<<<dim3(SEQ / 64, EMB / 32, BATCH), 256>>>(h);
    conv_w_kernel<<<EMB / 64, 256>>>(Wq, Wk);
    proj_f16_kernel<<<(BATCH * SEQ) / 64, 256, PJ_TOT>>>(bq, bk);
    score_f16_kernel<<<dim3(SEQ / 128, SEQ / 128, BATCH), 256, SC_TOT>>>();
    colstat_merge_kernel<<<(BATCH * SEQ) / 256, 256>>>();
    scale_hht_kernel<<<(int)(((size_t)BATCH * EMB * SEQ) / (8 * 256)), 256>>>();
    out_gemm_f16_kernel<<<dim3(EMB / 128, SEQ / 128, BATCH), 256, OSM_TOT>>>(out);
}